// round 3
// baseline (speedup 1.0000x reference)
#include <cuda_runtime.h>

// Problem constants (fixed shapes)
#define BQ   4
#define KC   24
#define DD   16
#define NPIX (512 * 1024)
#define KP   17

// k_accum tiling
#define TILE      512
#define SROW      513
#define TILES_PB  8
#define ABLOCKS   (NPIX / TILE / TILES_PB)   // 128 blocks per image

// ---------------- device scratch ----------------
__device__ float g_sums[BQ * KC * DD];
__device__ float g_counts[BQ * KC];
__device__ float g_centers[BQ * KC * DD];
__device__ float g_invc[BQ * KC];
__device__ float g_vtot;
__device__ float g_extra;

// ---------------- init ----------------
__global__ void k_init() {
    int t = blockIdx.x * blockDim.x + threadIdx.x;
    if (t < BQ * KC * DD) g_sums[t] = 0.f;
    if (t < BQ * KC) g_counts[t] = 0.f;
    if (t == 0) g_vtot = 0.f;
}

// ---------------- pass 1: double-buffered ballot-gather ----------------
__global__ void __launch_bounds__(256) k_accum(const float* __restrict__ data,
                                               const int*  __restrict__ labels) {
    __shared__ float s_data[2][DD * SROW];
    __shared__ int   s_lab[2][TILE];

    const int t = threadIdx.x;
    const int w = t >> 5;
    const int lane = t & 31;
    const int b = blockIdx.y;
    const float* dptr = data + (size_t)b * DD * NPIX;
    const int*   lptr = labels + (size_t)b * NPIX;

    const int c0 = w * 3, c1 = c0 + 1, c2 = c0 + 2;
    float a0 = 0.f, a1 = 0.f, a2 = 0.f;
    float n0 = 0.f, n1 = 0.f, n2 = 0.f;

    const int tile0 = blockIdx.x * TILES_PB;

    float4 r[8];
    int4 rlab;

    // prefetch tile 0
    {
        const int p4base = tile0 * (TILE / 4);
#pragma unroll
        for (int i = 0; i < 8; i++) {
            const int idx = t + i * 256;
            const int d = idx >> 7;
            const int pv = idx & 127;
            r[i] = reinterpret_cast<const float4*>(dptr + (size_t)d * NPIX)[p4base + pv];
        }
        if (t < TILE / 4) rlab = reinterpret_cast<const int4*>(lptr)[p4base + t];
    }

    for (int ti = 0; ti < TILES_PB; ti++) {
        const int p = ti & 1;

        // ---- commit prefetched regs -> smem buffer p ----
#pragma unroll
        for (int i = 0; i < 8; i++) {
            const int idx = t + i * 256;
            const int d = idx >> 7;
            const int pv = idx & 127;
            float* row = &s_data[p][d * SROW];
            row[pv]       = r[i].x;      // col = ((q&3)<<7)|(q>>2), q = 4*pv + comp
            row[128 + pv] = r[i].y;
            row[256 + pv] = r[i].z;
            row[384 + pv] = r[i].w;
        }
        if (t < TILE / 4) {
            s_lab[p][t * 4 + 0] = rlab.x;
            s_lab[p][t * 4 + 1] = rlab.y;
            s_lab[p][t * 4 + 2] = rlab.z;
            s_lab[p][t * 4 + 3] = rlab.w;
        }

        // ---- prefetch next tile (latency hidden by gather below) ----
        if (ti + 1 < TILES_PB) {
            const int p4base = (tile0 + ti + 1) * (TILE / 4);
#pragma unroll
            for (int i = 0; i < 8; i++) {
                const int idx = t + i * 256;
                const int d = idx >> 7;
                const int pv = idx & 127;
                r[i] = reinterpret_cast<const float4*>(dptr + (size_t)d * NPIX)[p4base + pv];
            }
            if (t < TILE / 4) rlab = reinterpret_cast<const int4*>(lptr)[p4base + t];
        }

        __syncthreads();   // single barrier per tile

        // ---- ballot-scan + register gather ----
        const float* myrow = &s_data[p][(lane & 15) * SROW];
        const int* labp = s_lab[p];
#pragma unroll 4
        for (int ch = 0; ch < TILE / 32; ch++) {
            const int lab = labp[ch * 32 + lane];
            unsigned m0 = __ballot_sync(0xffffffffu, lab == c0);
            unsigned m1 = __ballot_sync(0xffffffffu, lab == c1);
            unsigned m2 = __ballot_sync(0xffffffffu, lab == c2);
            n0 += (float)__popc(m0);
            n1 += (float)__popc(m1);
            n2 += (float)__popc(m2);
            const int basep = ch * 32;

#define GATHER(mask, acc)                                                      \
            while (mask) {                                                     \
                int p0 = __ffs(mask) - 1; mask &= mask - 1;                    \
                int p1 = p0;                                                   \
                bool two = (mask != 0);                                        \
                if (two) { p1 = __ffs(mask) - 1; mask &= mask - 1; }           \
                const int q = basep + ((lane < 16) ? p0 : p1);                 \
                const int col = ((q & 3) << 7) | (q >> 2);                     \
                const float v = myrow[col];                                    \
                if (two || lane < 16) acc += v;                                \
            }

            GATHER(m0, a0)
            GATHER(m1, a1)
            GATHER(m2, a2)
#undef GATHER
        }
        // no trailing sync needed: next STS (buf p^1) is ordered by next sync
        // against gathers of tile ti-1; gather of tile ti precedes next sync.
        __syncthreads();
    }

    a0 += __shfl_xor_sync(0xffffffffu, a0, 16);
    a1 += __shfl_xor_sync(0xffffffffu, a1, 16);
    a2 += __shfl_xor_sync(0xffffffffu, a2, 16);

    if (lane < 16) {
        atomicAdd(&g_sums[(b * KC + c0) * DD + lane], a0);
        atomicAdd(&g_sums[(b * KC + c1) * DD + lane], a1);
        atomicAdd(&g_sums[(b * KC + c2) * DD + lane], a2);
    }
    if (lane == 0) {
        atomicAdd(&g_counts[b * KC + c0], n0);
        atomicAdd(&g_counts[b * KC + c1], n1);
        atomicAdd(&g_counts[b * KC + c2], n2);
    }
}

// ---------------- centers + dist term + reg term + inv counts ----------------
__global__ void k_centers() {
    __shared__ float s_c[BQ * KC * DD];
    __shared__ float s_red[256];
    const int t = threadIdx.x;

    for (int i = t; i < BQ * KC * DD; i += 256) {
        const float c = g_sums[i] / g_counts[i >> 4];
        s_c[i] = c;
        g_centers[i] = c;
    }
    if (t < BQ * KC) g_invc[t] = 1.f / g_counts[t];
    __syncthreads();

    const float inv_pairs = 1.f / (2.f * KC * (KC - 1));
    float acc = 0.f;
    for (int i = t; i < BQ * KC * KC; i += 256) {
        const int b = i / (KC * KC);
        const int r = i - b * KC * KC;
        const int k1 = r / KC, k2 = r - k1 * KC;
        const float* c1 = &s_c[(b * KC + k1) * DD];
        const float* c2 = &s_c[(b * KC + k2) * DD];
        float sq = 0.f;
#pragma unroll
        for (int d = 0; d < DD; d++) { const float df = c1[d] - c2[d]; sq += df * df; }
        const float cd = (k1 == k2) ? 0.f : sqrtf(sq);
        const float h  = fmaxf(2.f - cd, 0.f);
        acc += h * h * inv_pairs;
    }
    for (int i = t; i < BQ * KC; i += 256) {
        const float* c = &s_c[i * DD];
        float sq = 0.f;
#pragma unroll
        for (int d = 0; d < DD; d++) sq += c[d] * c[d];
        acc += sqrtf(sq) * (1.f / KC);
    }

    s_red[t] = acc;
    __syncthreads();
    for (int s = 128; s > 0; s >>= 1) {
        if (t < s) s_red[t] += s_red[t + s];
        __syncthreads();
    }
    if (t == 0) g_extra = s_red[0];
}

// ---------------- pass 2: hinged variance, atomic-free, single wave ----------
__global__ void __launch_bounds__(256) k_var(const float* __restrict__ data,
                                             const int*  __restrict__ labels) {
    __shared__ float s_c[KC * KP];
    __shared__ float s_ic[KC];
    __shared__ float s_red[8];
    const int t = threadIdx.x;
    const int b = blockIdx.y;

    for (int i = t; i < KC * DD; i += 256)
        s_c[(i >> 4) * KP + (i & 15)] = g_centers[b * KC * DD + i];
    if (t < KC) s_ic[t] = g_invc[b * KC + t];
    __syncthreads();

    const float* dptr = data + (size_t)b * DD * NPIX;
    const int*   lptr = labels + (size_t)b * NPIX;

    // reversed block order: start where pass 1 ended -> L2 reuse
    const int bx = gridDim.x - 1 - blockIdx.x;
    const int vbase = bx * (256 * 4);

    float acc = 0.f;
#pragma unroll 2
    for (int it = 0; it < 4; it++) {
        const int vn = vbase + it * 256 + t;
        const int4 l4 = reinterpret_cast<const int4*>(lptr)[vn];
        const int o0 = l4.x * KP, o1 = l4.y * KP, o2 = l4.z * KP, o3 = l4.w * KP;
        float s0 = 0.f, s1 = 0.f, s2 = 0.f, s3 = 0.f;
#pragma unroll
        for (int d = 0; d < DD; d++) {
            const float4 v =
                reinterpret_cast<const float4*>(dptr + (size_t)d * NPIX)[vn];
            const float a0 = v.x - s_c[o0 + d]; s0 += a0 * a0;
            const float a1 = v.y - s_c[o1 + d]; s1 += a1 * a1;
            const float a2 = v.z - s_c[o2 + d]; s2 += a2 * a2;
            const float a3 = v.w - s_c[o3 + d]; s3 += a3 * a3;
        }
        const float h0 = fmaxf(sqrtf(s0) - 1.f, 0.f);
        const float h1 = fmaxf(sqrtf(s1) - 1.f, 0.f);
        const float h2 = fmaxf(sqrtf(s2) - 1.f, 0.f);
        const float h3 = fmaxf(sqrtf(s3) - 1.f, 0.f);
        acc += h0 * h0 * s_ic[l4.x];
        acc += h1 * h1 * s_ic[l4.y];
        acc += h2 * h2 * s_ic[l4.z];
        acc += h3 * h3 * s_ic[l4.w];
    }

#pragma unroll
    for (int o = 16; o > 0; o >>= 1)
        acc += __shfl_xor_sync(0xffffffffu, acc, o);
    if ((t & 31) == 0) s_red[t >> 5] = acc;
    __syncthreads();
    if (t < 8) {
        float v = s_red[t];
#pragma unroll
        for (int o = 4; o > 0; o >>= 1)
            v += __shfl_xor_sync(0xffu, v, o);
        if (t == 0) atomicAdd(&g_vtot, v);
    }
}

// ---------------- finalize ----------------
__global__ void k_final(float* __restrict__ out) {
    if (threadIdx.x == 0)
        out[0] = (g_vtot + g_extra) * (1.f / BQ);
}

// ---------------- entry point ----------------
extern "C" void kernel_launch(void* const* d_in, const int* in_sizes, int n_in,
                              void* d_out, int out_size) {
    const float* data   = (const float*)d_in[0];
    const int*   labels = (const int*)d_in[1];
    float* out = (float*)d_out;

    k_init<<<6, 256>>>();

    dim3 agrid(ABLOCKS, BQ);
    k_accum<<<agrid, 256>>>(data, labels);

    k_centers<<<1, 256>>>();

    dim3 vgrid(NPIX / 4096, BQ);
    k_var<<<vgrid, 256>>>(data, labels);

    k_final<<<1, 32>>>(out);
}

// round 4
// speedup vs baseline: 1.3655x; 1.3655x over previous
#include <cuda_runtime.h>

// Problem constants (fixed shapes)
#define BQ   4
#define KC   24
#define DD   16
#define NPIX (512 * 1024)
#define KP   17

// k_accum tiling
#define TILE      512
#define SROW      516          // floats; mult of 4 (STS.128 align), 516%32=4 -> 2-way LDS worst
#define TILES_PB  4
#define ABLOCKS   (NPIX / TILE / TILES_PB)   // 256 blocks per image

// ---------------- device scratch ----------------
__device__ float g_sums[BQ * KC * DD];
__device__ float g_counts[BQ * KC];
__device__ float g_centers[BQ * KC * DD];
__device__ float g_invc[BQ * KC];
__device__ float g_vtot;
__device__ float g_extra;

// ---------------- init ----------------
__global__ void k_init() {
    int t = blockIdx.x * blockDim.x + threadIdx.x;
    if (t < BQ * KC * DD) g_sums[t] = 0.f;
    if (t < BQ * KC) g_counts[t] = 0.f;
    if (t == 0) g_vtot = 0.f;
}

// ---------------- pass 1: ballot-gather, natural layout, predicated gather ----
__global__ void __launch_bounds__(256) k_accum(const float* __restrict__ data,
                                               const int*  __restrict__ labels) {
    __shared__ float s_data[DD * SROW];   // s_data[d*SROW + q], q = point in tile
    __shared__ int   s_lab[TILE];

    const int t = threadIdx.x;
    const int w = t >> 5;
    const int lane = t & 31;
    const int b = blockIdx.y;
    const float* dptr = data + (size_t)b * DD * NPIX;
    const int*   lptr = labels + (size_t)b * NPIX;

    const int c0 = w * 3, c1 = c0 + 1, c2 = c0 + 2;
    float a0 = 0.f, a1 = 0.f, a2 = 0.f;
    int   in0 = 0,  in1 = 0,  in2 = 0;

    const float* myrow = &s_data[(lane & 15) * SROW];

    for (int ti = 0; ti < TILES_PB; ti++) {
        const int tile = blockIdx.x * TILES_PB + ti;
        const int p4base = tile * (TILE / 4);

        // ---- stage: coalesced LDG.128 -> STS.128 (natural layout) ----
        if (t < TILE / 4) {
            const int4 l4 = reinterpret_cast<const int4*>(lptr)[p4base + t];
            *reinterpret_cast<int4*>(&s_lab[t * 4]) = l4;
        }
#pragma unroll
        for (int i = 0; i < 8; i++) {
            const int idx = t + i * 256;         // 0..2047
            const int d = idx >> 7;
            const int pv = idx & 127;            // float4 column
            const float4 v =
                reinterpret_cast<const float4*>(dptr + (size_t)d * NPIX)[p4base + pv];
            *reinterpret_cast<float4*>(&s_data[d * SROW + pv * 4]) = v;
        }
        __syncthreads();

        // ---- ballot-scan + predicated register gather ----
#pragma unroll 4
        for (int ch = 0; ch < TILE / 32; ch++) {
            const int lab = s_lab[ch * 32 + lane];
            unsigned m0 = __ballot_sync(0xffffffffu, lab == c0);
            unsigned m1 = __ballot_sync(0xffffffffu, lab == c1);
            unsigned m2 = __ballot_sync(0xffffffffu, lab == c2);
            in0 += __popc(m0);
            in1 += __popc(m1);
            in2 += __popc(m2);
            const float* rowp = myrow + ch * 32;

            // one dual-point step: lanes 0-15 take first set bit, 16-31 second
#define GSTEP(m, acc) {                                                        \
                const int pa = __ffs((int)(m)) - 1;                            \
                unsigned mm = (m) & ((m) - 1);                                 \
                const int pb = __ffs((int)mm) - 1;                             \
                mm &= mm - 1;                                                  \
                const int sel = (lane < 16) ? pa : pb;                         \
                if (sel >= 0) acc += rowp[sel];                                \
                (m) = mm; }

            GSTEP(m0, a0) GSTEP(m0, a0)
            if (m0) { do { GSTEP(m0, a0) } while (m0); }   // cnt>=5: ~1.7%
            GSTEP(m1, a1) GSTEP(m1, a1)
            if (m1) { do { GSTEP(m1, a1) } while (m1); }
            GSTEP(m2, a2) GSTEP(m2, a2)
            if (m2) { do { GSTEP(m2, a2) } while (m2); }
#undef GSTEP
        }
        __syncthreads();
    }

    // fold second-point half into first
    a0 += __shfl_xor_sync(0xffffffffu, a0, 16);
    a1 += __shfl_xor_sync(0xffffffffu, a1, 16);
    a2 += __shfl_xor_sync(0xffffffffu, a2, 16);

    if (lane < 16) {
        atomicAdd(&g_sums[(b * KC + c0) * DD + lane], a0);
        atomicAdd(&g_sums[(b * KC + c1) * DD + lane], a1);
        atomicAdd(&g_sums[(b * KC + c2) * DD + lane], a2);
    }
    if (lane == 0) {
        atomicAdd(&g_counts[b * KC + c0], (float)in0);
        atomicAdd(&g_counts[b * KC + c1], (float)in1);
        atomicAdd(&g_counts[b * KC + c2], (float)in2);
    }
}

// ---------------- centers + dist term + reg term + inv counts ----------------
__global__ void k_centers() {
    __shared__ float s_c[BQ * KC * DD];
    __shared__ float s_red[256];
    const int t = threadIdx.x;

    for (int i = t; i < BQ * KC * DD; i += 256) {
        const float c = g_sums[i] / g_counts[i >> 4];
        s_c[i] = c;
        g_centers[i] = c;
    }
    if (t < BQ * KC) g_invc[t] = 1.f / g_counts[t];
    __syncthreads();

    const float inv_pairs = 1.f / (2.f * KC * (KC - 1));
    float acc = 0.f;
    for (int i = t; i < BQ * KC * KC; i += 256) {
        const int b = i / (KC * KC);
        const int r = i - b * KC * KC;
        const int k1 = r / KC, k2 = r - k1 * KC;
        const float* c1 = &s_c[(b * KC + k1) * DD];
        const float* c2 = &s_c[(b * KC + k2) * DD];
        float sq = 0.f;
#pragma unroll
        for (int d = 0; d < DD; d++) { const float df = c1[d] - c2[d]; sq += df * df; }
        const float cd = (k1 == k2) ? 0.f : sqrtf(sq);
        const float h  = fmaxf(2.f - cd, 0.f);
        acc += h * h * inv_pairs;
    }
    for (int i = t; i < BQ * KC; i += 256) {
        const float* c = &s_c[i * DD];
        float sq = 0.f;
#pragma unroll
        for (int d = 0; d < DD; d++) sq += c[d] * c[d];
        acc += sqrtf(sq) * (1.f / KC);
    }

    s_red[t] = acc;
    __syncthreads();
    for (int s = 128; s > 0; s >>= 1) {
        if (t < s) s_red[t] += s_red[t + s];
        __syncthreads();
    }
    if (t == 0) g_extra = s_red[0];
}

// ---------------- pass 2: hinged variance (R2 config: 1024 blocks, 2 f4/thr) --
__global__ void __launch_bounds__(256) k_var(const float* __restrict__ data,
                                             const int*  __restrict__ labels) {
    __shared__ float s_c[KC * KP];
    __shared__ float s_ic[KC];
    __shared__ float s_red[8];
    const int t = threadIdx.x;
    const int b = blockIdx.y;

    for (int i = t; i < KC * DD; i += 256)
        s_c[(i >> 4) * KP + (i & 15)] = g_centers[b * KC * DD + i];
    if (t < KC) s_ic[t] = g_invc[b * KC + t];
    __syncthreads();

    const float* dptr = data + (size_t)b * DD * NPIX;
    const int*   lptr = labels + (size_t)b * NPIX;

    const int bx = gridDim.x - 1 - blockIdx.x;   // reversed: L2 reuse from pass 1
    const int vbase = bx * (256 * 2);

    float acc = 0.f;
#pragma unroll
    for (int it = 0; it < 2; it++) {
        const int vn = vbase + it * 256 + t;
        const int4 l4 = reinterpret_cast<const int4*>(lptr)[vn];
        const int o0 = l4.x * KP, o1 = l4.y * KP, o2 = l4.z * KP, o3 = l4.w * KP;
        float s0 = 0.f, s1 = 0.f, s2 = 0.f, s3 = 0.f;
#pragma unroll
        for (int d = 0; d < DD; d++) {
            const float4 v =
                reinterpret_cast<const float4*>(dptr + (size_t)d * NPIX)[vn];
            const float a0 = v.x - s_c[o0 + d]; s0 += a0 * a0;
            const float a1 = v.y - s_c[o1 + d]; s1 += a1 * a1;
            const float a2 = v.z - s_c[o2 + d]; s2 += a2 * a2;
            const float a3 = v.w - s_c[o3 + d]; s3 += a3 * a3;
        }
        const float h0 = fmaxf(sqrtf(s0) - 1.f, 0.f);
        const float h1 = fmaxf(sqrtf(s1) - 1.f, 0.f);
        const float h2 = fmaxf(sqrtf(s2) - 1.f, 0.f);
        const float h3 = fmaxf(sqrtf(s3) - 1.f, 0.f);
        acc += h0 * h0 * s_ic[l4.x];
        acc += h1 * h1 * s_ic[l4.y];
        acc += h2 * h2 * s_ic[l4.z];
        acc += h3 * h3 * s_ic[l4.w];
    }

#pragma unroll
    for (int o = 16; o > 0; o >>= 1)
        acc += __shfl_xor_sync(0xffffffffu, acc, o);
    if ((t & 31) == 0) s_red[t >> 5] = acc;
    __syncthreads();
    if (t < 8) {
        float v = s_red[t];
#pragma unroll
        for (int o = 4; o > 0; o >>= 1)
            v += __shfl_xor_sync(0xffu, v, o);
        if (t == 0) atomicAdd(&g_vtot, v);
    }
}

// ---------------- finalize ----------------
__global__ void k_final(float* __restrict__ out) {
    if (threadIdx.x == 0)
        out[0] = (g_vtot + g_extra) * (1.f / BQ);
}

// ---------------- entry point ----------------
extern "C" void kernel_launch(void* const* d_in, const int* in_sizes, int n_in,
                              void* d_out, int out_size) {
    const float* data   = (const float*)d_in[0];
    const int*   labels = (const int*)d_in[1];
    float* out = (float*)d_out;

    k_init<<<6, 256>>>();

    dim3 agrid(ABLOCKS, BQ);
    k_accum<<<agrid, 256>>>(data, labels);

    k_centers<<<1, 256>>>();

    dim3 vgrid(NPIX / 2048, BQ);
    k_var<<<vgrid, 256>>>(data, labels);

    k_final<<<1, 32>>>(out);
}

// round 5
// speedup vs baseline: 1.4238x; 1.0427x over previous
#include <cuda_runtime.h>
#include <cstdint>

// Problem constants (fixed shapes)
#define BQ   4
#define KC   24
#define DD   16
#define NPIX (512 * 1024)
#define KP   17

// k_accum tiling
#define TILE      256
#define SROW      260          // floats; mult of 4 for 16B cp.async dst alignment
#define TILES_PB  8
#define ABLOCKS   (NPIX / TILE / TILES_PB)   // 256 blocks per image

// ---------------- device scratch ----------------
__device__ float g_sums[BQ * KC * DD];
__device__ float g_counts[BQ * KC];
__device__ float g_centers[BQ * KC * DD];
__device__ float g_invc[BQ * KC];
__device__ float g_vtot;
__device__ float g_extra;

// ---------------- cp.async helpers ----------------
__device__ __forceinline__ void cp16(uint32_t dst, const void* src) {
    asm volatile("cp.async.cg.shared.global [%0], [%1], 16;" :: "r"(dst), "l"(src));
}
__device__ __forceinline__ void cp_commit() {
    asm volatile("cp.async.commit_group;");
}
template <int N>
__device__ __forceinline__ void cp_wait() {
    asm volatile("cp.async.wait_group %0;" :: "n"(N));
}

// ---------------- init ----------------
__global__ void k_init() {
    int t = blockIdx.x * blockDim.x + threadIdx.x;
    if (t < BQ * KC * DD) g_sums[t] = 0.f;
    if (t < BQ * KC) g_counts[t] = 0.f;
    if (t == 0) g_vtot = 0.f;
}

// ---------------- pass 1: cp.async double-buffered ballot-gather --------------
__global__ void __launch_bounds__(256) k_accum(const float* __restrict__ data,
                                               const int*  __restrict__ labels) {
    __shared__ float s_data[2][DD * SROW];   // natural layout: [d][q]
    __shared__ int   s_lab[2][TILE];

    const int t = threadIdx.x;
    const int w = t >> 5;
    const int lane = t & 31;
    const int b = blockIdx.y;
    const float* dptr = data + (size_t)b * DD * NPIX;
    const int*   lptr = labels + (size_t)b * NPIX;

    const uint32_t sd_addr = (uint32_t)__cvta_generic_to_shared(&s_data[0][0]);
    const uint32_t sl_addr = (uint32_t)__cvta_generic_to_shared(&s_lab[0][0]);

    const int c0 = w * 3, c1 = c0 + 1, c2 = c0 + 2;
    float a0 = 0.f, a1 = 0.f, a2 = 0.f;
    int   in0 = 0,  in1 = 0,  in2 = 0;

    const int tile0 = blockIdx.x * TILES_PB;

    // issue all cp.asyncs for one tile into buffer p
#define ISSUE(tile, p) {                                                       \
        const int p4b = (tile) * (TILE / 4);                                   \
        const uint32_t dbase = sd_addr + (p) * (DD * SROW * 4);                \
        _Pragma("unroll")                                                      \
        for (int i = 0; i < 4; i++) {                                          \
            const int idx = t + i * 256;                                       \
            const int d = idx >> 6;                                            \
            const int pv = idx & 63;                                           \
            cp16(dbase + (uint32_t)(d * SROW + pv * 4) * 4,                    \
                 dptr + (size_t)d * NPIX + (size_t)(p4b + pv) * 4);            \
        }                                                                      \
        if (t < TILE / 4)                                                      \
            cp16(sl_addr + (p) * (TILE * 4) + t * 16,                          \
                 lptr + (size_t)p4b * 4 + (size_t)t * 4);                      \
    }

    ISSUE(tile0, 0)
    cp_commit();

    for (int ti = 0; ti < TILES_PB; ti++) {
        const int p = ti & 1;

        if (ti + 1 < TILES_PB) {
            ISSUE(tile0 + ti + 1, p ^ 1)
            cp_commit();
            cp_wait<1>();       // tile ti fully arrived (only ti+1 pending)
        } else {
            cp_wait<0>();
        }
        __syncthreads();

        // ---- ballot-scan + register gather (R2-style while loop) ----
        const float* myrow = &s_data[p][(lane & 15) * SROW];
        const int* labp = s_lab[p];
#pragma unroll
        for (int ch = 0; ch < TILE / 32; ch++) {
            const int lab = labp[ch * 32 + lane];
            unsigned m0 = __ballot_sync(0xffffffffu, lab == c0);
            unsigned m1 = __ballot_sync(0xffffffffu, lab == c1);
            unsigned m2 = __ballot_sync(0xffffffffu, lab == c2);
            in0 += __popc(m0);
            in1 += __popc(m1);
            in2 += __popc(m2);
            const float* rowp = myrow + ch * 32;

#define GATHER(mask, acc)                                                      \
            while (mask) {                                                     \
                int p0 = __ffs(mask) - 1; mask &= mask - 1;                    \
                int p1 = p0;                                                   \
                bool two = (mask != 0);                                        \
                if (two) { p1 = __ffs(mask) - 1; mask &= mask - 1; }           \
                const float v = rowp[(lane < 16) ? p0 : p1];                   \
                if (two || lane < 16) acc += v;                                \
            }

            GATHER(m0, a0)
            GATHER(m1, a1)
            GATHER(m2, a2)
#undef GATHER
        }
        __syncthreads();  // before next iteration's ISSUE overwrites buffer p
    }
#undef ISSUE

    a0 += __shfl_xor_sync(0xffffffffu, a0, 16);
    a1 += __shfl_xor_sync(0xffffffffu, a1, 16);
    a2 += __shfl_xor_sync(0xffffffffu, a2, 16);

    if (lane < 16) {
        atomicAdd(&g_sums[(b * KC + c0) * DD + lane], a0);
        atomicAdd(&g_sums[(b * KC + c1) * DD + lane], a1);
        atomicAdd(&g_sums[(b * KC + c2) * DD + lane], a2);
    }
    if (lane == 0) {
        atomicAdd(&g_counts[b * KC + c0], (float)in0);
        atomicAdd(&g_counts[b * KC + c1], (float)in1);
        atomicAdd(&g_counts[b * KC + c2], (float)in2);
    }
}

// ---------------- centers + dist term + reg term + inv counts ----------------
__global__ void k_centers() {
    __shared__ float s_c[BQ * KC * DD];
    __shared__ float s_red[256];
    const int t = threadIdx.x;

    for (int i = t; i < BQ * KC * DD; i += 256) {
        const float c = g_sums[i] / g_counts[i >> 4];
        s_c[i] = c;
        g_centers[i] = c;
    }
    if (t < BQ * KC) g_invc[t] = 1.f / g_counts[t];
    __syncthreads();

    const float inv_pairs = 1.f / (2.f * KC * (KC - 1));
    float acc = 0.f;
    for (int i = t; i < BQ * KC * KC; i += 256) {
        const int b = i / (KC * KC);
        const int r = i - b * KC * KC;
        const int k1 = r / KC, k2 = r - k1 * KC;
        const float* c1 = &s_c[(b * KC + k1) * DD];
        const float* c2 = &s_c[(b * KC + k2) * DD];
        float sq = 0.f;
#pragma unroll
        for (int d = 0; d < DD; d++) { const float df = c1[d] - c2[d]; sq += df * df; }
        const float cd = (k1 == k2) ? 0.f : sqrtf(sq);
        const float h  = fmaxf(2.f - cd, 0.f);
        acc += h * h * inv_pairs;
    }
    for (int i = t; i < BQ * KC; i += 256) {
        const float* c = &s_c[i * DD];
        float sq = 0.f;
#pragma unroll
        for (int d = 0; d < DD; d++) sq += c[d] * c[d];
        acc += sqrtf(sq) * (1.f / KC);
    }

    s_red[t] = acc;
    __syncthreads();
    for (int s = 128; s > 0; s >>= 1) {
        if (t < s) s_red[t] += s_red[t + s];
        __syncthreads();
    }
    if (t == 0) g_extra = s_red[0];
}

// ---------------- pass 2: hinged variance (best config: 1024 blocks) ----------
__global__ void __launch_bounds__(256) k_var(const float* __restrict__ data,
                                             const int*  __restrict__ labels) {
    __shared__ float s_c[KC * KP];
    __shared__ float s_ic[KC];
    __shared__ float s_red[8];
    const int t = threadIdx.x;
    const int b = blockIdx.y;

    for (int i = t; i < KC * DD; i += 256)
        s_c[(i >> 4) * KP + (i & 15)] = g_centers[b * KC * DD + i];
    if (t < KC) s_ic[t] = g_invc[b * KC + t];
    __syncthreads();

    const float* dptr = data + (size_t)b * DD * NPIX;
    const int*   lptr = labels + (size_t)b * NPIX;

    const int bx = gridDim.x - 1 - blockIdx.x;   // reversed: L2 reuse from pass 1
    const int vbase = bx * (256 * 2);

    float acc = 0.f;
#pragma unroll
    for (int it = 0; it < 2; it++) {
        const int vn = vbase + it * 256 + t;
        const int4 l4 = reinterpret_cast<const int4*>(lptr)[vn];
        const int o0 = l4.x * KP, o1 = l4.y * KP, o2 = l4.z * KP, o3 = l4.w * KP;
        float s0 = 0.f, s1 = 0.f, s2 = 0.f, s3 = 0.f;
#pragma unroll
        for (int d = 0; d < DD; d++) {
            const float4 v =
                reinterpret_cast<const float4*>(dptr + (size_t)d * NPIX)[vn];
            const float a0 = v.x - s_c[o0 + d]; s0 += a0 * a0;
            const float a1 = v.y - s_c[o1 + d]; s1 += a1 * a1;
            const float a2 = v.z - s_c[o2 + d]; s2 += a2 * a2;
            const float a3 = v.w - s_c[o3 + d]; s3 += a3 * a3;
        }
        const float h0 = fmaxf(sqrtf(s0) - 1.f, 0.f);
        const float h1 = fmaxf(sqrtf(s1) - 1.f, 0.f);
        const float h2 = fmaxf(sqrtf(s2) - 1.f, 0.f);
        const float h3 = fmaxf(sqrtf(s3) - 1.f, 0.f);
        acc += h0 * h0 * s_ic[l4.x];
        acc += h1 * h1 * s_ic[l4.y];
        acc += h2 * h2 * s_ic[l4.z];
        acc += h3 * h3 * s_ic[l4.w];
    }

#pragma unroll
    for (int o = 16; o > 0; o >>= 1)
        acc += __shfl_xor_sync(0xffffffffu, acc, o);
    if ((t & 31) == 0) s_red[t >> 5] = acc;
    __syncthreads();
    if (t < 8) {
        float v = s_red[t];
#pragma unroll
        for (int o = 4; o > 0; o >>= 1)
            v += __shfl_xor_sync(0xffu, v, o);
        if (t == 0) atomicAdd(&g_vtot, v);
    }
}

// ---------------- finalize ----------------
__global__ void k_final(float* __restrict__ out) {
    if (threadIdx.x == 0)
        out[0] = (g_vtot + g_extra) * (1.f / BQ);
}

// ---------------- entry point ----------------
extern "C" void kernel_launch(void* const* d_in, const int* in_sizes, int n_in,
                              void* d_out, int out_size) {
    const float* data   = (const float*)d_in[0];
    const int*   labels = (const int*)d_in[1];
    float* out = (float*)d_out;

    k_init<<<6, 256>>>();

    dim3 agrid(ABLOCKS, BQ);
    k_accum<<<agrid, 256>>>(data, labels);

    k_centers<<<1, 256>>>();

    dim3 vgrid(NPIX / 2048, BQ);
    k_var<<<vgrid, 256>>>(data, labels);

    k_final<<<1, 32>>>(out);
}

// round 6
// speedup vs baseline: 1.5333x; 1.0770x over previous
#include <cuda_runtime.h>
#include <cstdint>

// Problem constants (fixed shapes)
#define BQ   4
#define KC   24
#define DD   16
#define NPIX (512 * 1024)
#define KP   17

// k_accum tiling
#define TILE        256
#define QROW        17                    // floats per point row (16 dims + pad)
#define TILES_IMG   (NPIX / TILE)         // 2048 tiles per image
#define ABLK_X      185                   // blocks per image (x); 185*4 = 740 = 5/SM

// ---------------- device scratch ----------------
__device__ float g_sums[BQ * KC * DD];
__device__ float g_counts[BQ * KC];
__device__ float g_centers[BQ * KC * DD];
__device__ float g_invc[BQ * KC];
__device__ float g_vtot;
__device__ float g_extra;

// ---------------- init ----------------
__global__ void k_init() {
    int t = blockIdx.x * blockDim.x + threadIdx.x;
    if (t < BQ * KC * DD) g_sums[t] = 0.f;
    if (t < BQ * KC) g_counts[t] = 0.f;
    if (t == 0) g_vtot = 0.f;
}

// ---------------- pass 1: per-warp-chunk smem RMW (no ballots, no atomics) ----
__global__ void __launch_bounds__(256) k_accum(const float* __restrict__ data,
                                               const int*  __restrict__ labels) {
    __shared__ float s_data[TILE * QROW];          // point-major: [q][d], stride 17
    __shared__ int   s_lab[TILE];
    __shared__ float s_acc[8 * 2 * KC * DD];       // [warp][half][cluster][dim]
    __shared__ float s_cnt[8 * 2 * KC];            // [warp][half][cluster]

    const int t = threadIdx.x;
    const int w = t >> 5;
    const int lane = t & 31;
    const int half = lane >> 4;                    // 0: point A, 1: point B
    const int dlane = lane & 15;                   // dim

    const int b = blockIdx.y;
    const float* dptr = data + (size_t)b * DD * NPIX;
    const int*   lptr = labels + (size_t)b * NPIX;

    // zero accumulators
    for (int i = t; i < 8 * 2 * KC * DD; i += 256) s_acc[i] = 0.f;
    for (int i = t; i < 8 * 2 * KC; i += 256) s_cnt[i] = 0.f;
    __syncthreads();

    const int vbase0   = (w * 32 + half) * QROW + dlane;          // smem float idx
    float* accb = &s_acc[((w * 2 + half) * KC) * DD + dlane];
    float* cntb = &s_cnt[(w * 2 + half) * KC];
    const bool do_cnt = (dlane == 0);

    for (int tile = blockIdx.x; tile < TILES_IMG; tile += ABLK_X) {
        const int p4base = tile * (TILE / 4);

        // ---- stage labels + data (point-major) ----
        if (t < TILE / 4)
            reinterpret_cast<int4*>(s_lab)[t] =
                reinterpret_cast<const int4*>(lptr)[p4base + t];
#pragma unroll
        for (int i = 0; i < 4; i++) {
            const int idx = t + i * 256;           // 0..1023
            const int d  = idx >> 6;               // dim
            const int pv = idx & 63;               // float4 col
            const float4 v =
                reinterpret_cast<const float4*>(dptr + (size_t)d * NPIX)[p4base + pv];
            const int q0 = pv * 4;
            s_data[(q0 + 0) * QROW + d] = v.x;
            s_data[(q0 + 1) * QROW + d] = v.y;
            s_data[(q0 + 2) * QROW + d] = v.z;
            s_data[(q0 + 3) * QROW + d] = v.w;
        }
        __syncthreads();

        // ---- gather: warp w owns chunk w (points w*32 .. w*32+31) ----
        const int labReg = s_lab[w * 32 + lane];
#pragma unroll
        for (int i = 0; i < 16; i++) {
            const int myl = __shfl_sync(0xffffffffu, labReg, 2 * i + half);
            const float v = s_data[vbase0 + i * (2 * QROW)];
            float* pa = accb + myl * DD;
            *pa += v;
            if (do_cnt) cntb[myl] += 1.0f;
        }
        __syncthreads();   // protect s_data/s_lab before next stage
    }

    // ---- merge 16 copies -> global ----
    for (int o = t; o < KC * DD; o += 256) {
        float s = 0.f;
#pragma unroll
        for (int c = 0; c < 16; c++) s += s_acc[c * (KC * DD) + o];
        atomicAdd(&g_sums[b * KC * DD + o], s);
    }
    if (t < KC) {
        float s = 0.f;
#pragma unroll
        for (int c = 0; c < 16; c++) s += s_cnt[c * KC + t];
        atomicAdd(&g_counts[b * KC + t], s);
    }
}

// ---------------- centers + dist term + reg term + inv counts ----------------
__global__ void k_centers() {
    __shared__ float s_c[BQ * KC * DD];
    __shared__ float s_red[256];
    const int t = threadIdx.x;

    for (int i = t; i < BQ * KC * DD; i += 256) {
        const float c = g_sums[i] / g_counts[i >> 4];
        s_c[i] = c;
        g_centers[i] = c;
    }
    if (t < BQ * KC) g_invc[t] = 1.f / g_counts[t];
    __syncthreads();

    const float inv_pairs = 1.f / (2.f * KC * (KC - 1));
    float acc = 0.f;
    for (int i = t; i < BQ * KC * KC; i += 256) {
        const int b = i / (KC * KC);
        const int r = i - b * KC * KC;
        const int k1 = r / KC, k2 = r - k1 * KC;
        const float* c1 = &s_c[(b * KC + k1) * DD];
        const float* c2 = &s_c[(b * KC + k2) * DD];
        float sq = 0.f;
#pragma unroll
        for (int d = 0; d < DD; d++) { const float df = c1[d] - c2[d]; sq += df * df; }
        const float cd = (k1 == k2) ? 0.f : sqrtf(sq);
        const float h  = fmaxf(2.f - cd, 0.f);
        acc += h * h * inv_pairs;
    }
    for (int i = t; i < BQ * KC; i += 256) {
        const float* c = &s_c[i * DD];
        float sq = 0.f;
#pragma unroll
        for (int d = 0; d < DD; d++) sq += c[d] * c[d];
        acc += sqrtf(sq) * (1.f / KC);
    }

    s_red[t] = acc;
    __syncthreads();
    for (int s = 128; s > 0; s >>= 1) {
        if (t < s) s_red[t] += s_red[t + s];
        __syncthreads();
    }
    if (t == 0) g_extra = s_red[0];
}

// ---------------- pass 2: hinged variance (best config: 1024 blocks) ----------
__global__ void __launch_bounds__(256) k_var(const float* __restrict__ data,
                                             const int*  __restrict__ labels) {
    __shared__ float s_c[KC * KP];
    __shared__ float s_ic[KC];
    __shared__ float s_red[8];
    const int t = threadIdx.x;
    const int b = blockIdx.y;

    for (int i = t; i < KC * DD; i += 256)
        s_c[(i >> 4) * KP + (i & 15)] = g_centers[b * KC * DD + i];
    if (t < KC) s_ic[t] = g_invc[b * KC + t];
    __syncthreads();

    const float* dptr = data + (size_t)b * DD * NPIX;
    const int*   lptr = labels + (size_t)b * NPIX;

    const int bx = gridDim.x - 1 - blockIdx.x;   // reversed: L2 reuse from pass 1
    const int vbase = bx * (256 * 2);

    float acc = 0.f;
#pragma unroll
    for (int it = 0; it < 2; it++) {
        const int vn = vbase + it * 256 + t;
        const int4 l4 = reinterpret_cast<const int4*>(lptr)[vn];
        const int o0 = l4.x * KP, o1 = l4.y * KP, o2 = l4.z * KP, o3 = l4.w * KP;
        float s0 = 0.f, s1 = 0.f, s2 = 0.f, s3 = 0.f;
#pragma unroll
        for (int d = 0; d < DD; d++) {
            const float4 v =
                reinterpret_cast<const float4*>(dptr + (size_t)d * NPIX)[vn];
            const float a0 = v.x - s_c[o0 + d]; s0 += a0 * a0;
            const float a1 = v.y - s_c[o1 + d]; s1 += a1 * a1;
            const float a2 = v.z - s_c[o2 + d]; s2 += a2 * a2;
            const float a3 = v.w - s_c[o3 + d]; s3 += a3 * a3;
        }
        const float h0 = fmaxf(sqrtf(s0) - 1.f, 0.f);
        const float h1 = fmaxf(sqrtf(s1) - 1.f, 0.f);
        const float h2 = fmaxf(sqrtf(s2) - 1.f, 0.f);
        const float h3 = fmaxf(sqrtf(s3) - 1.f, 0.f);
        acc += h0 * h0 * s_ic[l4.x];
        acc += h1 * h1 * s_ic[l4.y];
        acc += h2 * h2 * s_ic[l4.z];
        acc += h3 * h3 * s_ic[l4.w];
    }

#pragma unroll
    for (int o = 16; o > 0; o >>= 1)
        acc += __shfl_xor_sync(0xffffffffu, acc, o);
    if ((t & 31) == 0) s_red[t >> 5] = acc;
    __syncthreads();
    if (t < 8) {
        float v = s_red[t];
#pragma unroll
        for (int o = 4; o > 0; o >>= 1)
            v += __shfl_xor_sync(0xffu, v, o);
        if (t == 0) atomicAdd(&g_vtot, v);
    }
}

// ---------------- finalize ----------------
__global__ void k_final(float* __restrict__ out) {
    if (threadIdx.x == 0)
        out[0] = (g_vtot + g_extra) * (1.f / BQ);
}

// ---------------- entry point ----------------
extern "C" void kernel_launch(void* const* d_in, const int* in_sizes, int n_in,
                              void* d_out, int out_size) {
    const float* data   = (const float*)d_in[0];
    const int*   labels = (const int*)d_in[1];
    float* out = (float*)d_out;

    k_init<<<6, 256>>>();

    dim3 agrid(ABLK_X, BQ);
    k_accum<<<agrid, 256>>>(data, labels);

    k_centers<<<1, 256>>>();

    dim3 vgrid(NPIX / 2048, BQ);
    k_var<<<vgrid, 256>>>(data, labels);

    k_final<<<1, 32>>>(out);
}

// round 7
// speedup vs baseline: 1.7683x; 1.1532x over previous
#include <cuda_runtime.h>
#include <cstdint>

// Problem constants (fixed shapes)
#define BQ   4
#define KC   24
#define DD   16
#define NPIX (512 * 1024)
#define KP   17

// k_accum tiling
#define TILE        256
#define QROW        17                    // floats per point row (16 dims + pad)
#define TILES_IMG   (NPIX / TILE)         // 2048 tiles per image
#define ABLK_X      185                   // 185*4 = 740 blocks ≈ 5/SM one wave

// ---------------- device scratch ----------------
__device__ float g_sums[BQ * KC * DD];
__device__ float g_counts[BQ * KC];
__device__ float g_centers[BQ * KC * DD];
__device__ float g_invc[BQ * KC];
__device__ float g_vtot;
__device__ float g_extra;

// ---------------- init ----------------
__global__ void k_init() {
    int t = blockIdx.x * blockDim.x + threadIdx.x;
    if (t < BQ * KC * DD) g_sums[t] = 0.f;
    if (t < BQ * KC) g_counts[t] = 0.f;
    if (t == 0) g_vtot = 0.f;
}

// ---------------- pass 0: label histogram (counts only) ----------------
__global__ void __launch_bounds__(256) k_count(const int* __restrict__ labels) {
    __shared__ int s_h[8][KC + 8];        // per-warp copies, padded
    const int t = threadIdx.x;
    const int w = t >> 5;
    const int b = blockIdx.y;
    const int* lptr = labels + (size_t)b * NPIX;

    for (int i = t; i < 8 * (KC + 8); i += 256)
        (&s_h[0][0])[i] = 0;
    __syncthreads();

    // 64 blocks per image, each thread 32 int4 = 128 labels
    const int base = blockIdx.x * (256 * 32);
#pragma unroll 4
    for (int i = 0; i < 32; i++) {
        const int4 l4 = reinterpret_cast<const int4*>(lptr)[base + i * 256 + t];
        atomicAdd(&s_h[w][l4.x], 1);
        atomicAdd(&s_h[w][l4.y], 1);
        atomicAdd(&s_h[w][l4.z], 1);
        atomicAdd(&s_h[w][l4.w], 1);
    }
    __syncthreads();

    if (t < KC) {
        int s = 0;
#pragma unroll
        for (int c = 0; c < 8; c++) s += s_h[c][t];
        atomicAdd(&g_counts[b * KC + t], (float)s);
    }
}

// ---------------- pass 1: half-warp smem RMW, conflict-free staging ----------
__global__ void __launch_bounds__(256) k_accum(const float* __restrict__ data,
                                               const int*  __restrict__ labels) {
    __shared__ float s_data[TILE * QROW];          // [q][d-rotated], stride 17
    __shared__ float s_acc[8 * 2 * KC * DD];       // [warp][half][cluster][dim]

    const int t = threadIdx.x;
    const int w = t >> 5;
    const int lane = t & 31;
    const int half = lane >> 4;                    // which of 2 concurrent points
    const int dlane = lane & 15;                   // dim

    const int b = blockIdx.y;
    const float* dptr = data + (size_t)b * DD * NPIX;
    const int*   lptr = labels + (size_t)b * NPIX;

    for (int i = t; i < 8 * 2 * KC * DD; i += 256) s_acc[i] = 0.f;
    __syncthreads();

    // gather-side rotated dim: rotation amount = (q>>5)&3 = w&3 (const per warp)
    const int drot = (dlane + (w & 3)) & 15;
    const float* myrow0 = &s_data[(w * 32 + half) * QROW + drot];
    float* accb = &s_acc[((w * 2 + half) * KC) * DD + dlane];

    for (int tile = blockIdx.x; tile < TILES_IMG; tile += ABLK_X) {
        const int p4base = tile * (TILE / 4);

        // label of this lane's own point (coalesced 128B per warp)
        const int labReg = lptr[tile * TILE + w * 32 + lane];

        // ---- stage data: LDG.128 d-major -> rotated scalar STS (conflict-free)
#pragma unroll
        for (int i = 0; i < 4; i++) {
            const int idx = t + i * 256;           // 0..1023
            const int d  = idx >> 6;               // dim
            const int pv = idx & 63;               // float4 col
            const float4 v =
                reinterpret_cast<const float4*>(dptr + (size_t)d * NPIX)[p4base + pv];
            const int dd = (d + ((pv >> 3) & 3)) & 15;   // rotated dim slot
            float* rp = &s_data[(pv * 4) * QROW + dd];
            rp[0 * QROW] = v.x;
            rp[1 * QROW] = v.y;
            rp[2 * QROW] = v.z;
            rp[3 * QROW] = v.w;
        }
        __syncthreads();

        // ---- gather: warp w owns its own chunk (points w*32 .. w*32+31) ----
#pragma unroll
        for (int i = 0; i < 16; i++) {
            const int myl = __shfl_sync(0xffffffffu, labReg, 2 * i + half);
            const float v = myrow0[i * (2 * QROW)];
            float* pa = accb + myl * DD;
            *pa += v;
        }
        __syncthreads();   // protect s_data before next stage
    }

    // ---- merge 16 copies -> global ----
    for (int o = t; o < KC * DD; o += 256) {
        float s = 0.f;
#pragma unroll
        for (int c = 0; c < 16; c++) s += s_acc[c * (KC * DD) + o];
        atomicAdd(&g_sums[b * KC * DD + o], s);
    }
}

// ---------------- centers + dist term + reg term + inv counts ----------------
__global__ void k_centers() {
    __shared__ float s_c[BQ * KC * DD];
    __shared__ float s_red[256];
    const int t = threadIdx.x;

    for (int i = t; i < BQ * KC * DD; i += 256) {
        const float c = g_sums[i] / g_counts[i >> 4];
        s_c[i] = c;
        g_centers[i] = c;
    }
    if (t < BQ * KC) g_invc[t] = 1.f / g_counts[t];
    __syncthreads();

    const float inv_pairs = 1.f / (2.f * KC * (KC - 1));
    float acc = 0.f;
    for (int i = t; i < BQ * KC * KC; i += 256) {
        const int b = i / (KC * KC);
        const int r = i - b * KC * KC;
        const int k1 = r / KC, k2 = r - k1 * KC;
        const float* c1 = &s_c[(b * KC + k1) * DD];
        const float* c2 = &s_c[(b * KC + k2) * DD];
        float sq = 0.f;
#pragma unroll
        for (int d = 0; d < DD; d++) { const float df = c1[d] - c2[d]; sq += df * df; }
        const float cd = (k1 == k2) ? 0.f : sqrtf(sq);
        const float h  = fmaxf(2.f - cd, 0.f);
        acc += h * h * inv_pairs;
    }
    for (int i = t; i < BQ * KC; i += 256) {
        const float* c = &s_c[i * DD];
        float sq = 0.f;
#pragma unroll
        for (int d = 0; d < DD; d++) sq += c[d] * c[d];
        acc += sqrtf(sq) * (1.f / KC);
    }

    s_red[t] = acc;
    __syncthreads();
    for (int s = 128; s > 0; s >>= 1) {
        if (t < s) s_red[t] += s_red[t + s];
        __syncthreads();
    }
    if (t == 0) g_extra = s_red[0];
}

// ---------------- pass 2: hinged variance (best config: 1024 blocks) ----------
__global__ void __launch_bounds__(256) k_var(const float* __restrict__ data,
                                             const int*  __restrict__ labels) {
    __shared__ float s_c[KC * KP];
    __shared__ float s_ic[KC];
    __shared__ float s_red[8];
    const int t = threadIdx.x;
    const int b = blockIdx.y;

    for (int i = t; i < KC * DD; i += 256)
        s_c[(i >> 4) * KP + (i & 15)] = g_centers[b * KC * DD + i];
    if (t < KC) s_ic[t] = g_invc[b * KC + t];
    __syncthreads();

    const float* dptr = data + (size_t)b * DD * NPIX;
    const int*   lptr = labels + (size_t)b * NPIX;

    const int bx = gridDim.x - 1 - blockIdx.x;   // reversed: L2 reuse from pass 1
    const int vbase = bx * (256 * 2);

    float acc = 0.f;
#pragma unroll
    for (int it = 0; it < 2; it++) {
        const int vn = vbase + it * 256 + t;
        const int4 l4 = reinterpret_cast<const int4*>(lptr)[vn];
        const int o0 = l4.x * KP, o1 = l4.y * KP, o2 = l4.z * KP, o3 = l4.w * KP;
        float s0 = 0.f, s1 = 0.f, s2 = 0.f, s3 = 0.f;
#pragma unroll
        for (int d = 0; d < DD; d++) {
            const float4 v =
                reinterpret_cast<const float4*>(dptr + (size_t)d * NPIX)[vn];
            const float a0 = v.x - s_c[o0 + d]; s0 += a0 * a0;
            const float a1 = v.y - s_c[o1 + d]; s1 += a1 * a1;
            const float a2 = v.z - s_c[o2 + d]; s2 += a2 * a2;
            const float a3 = v.w - s_c[o3 + d]; s3 += a3 * a3;
        }
        const float h0 = fmaxf(sqrtf(s0) - 1.f, 0.f);
        const float h1 = fmaxf(sqrtf(s1) - 1.f, 0.f);
        const float h2 = fmaxf(sqrtf(s2) - 1.f, 0.f);
        const float h3 = fmaxf(sqrtf(s3) - 1.f, 0.f);
        acc += h0 * h0 * s_ic[l4.x];
        acc += h1 * h1 * s_ic[l4.y];
        acc += h2 * h2 * s_ic[l4.z];
        acc += h3 * h3 * s_ic[l4.w];
    }

#pragma unroll
    for (int o = 16; o > 0; o >>= 1)
        acc += __shfl_xor_sync(0xffffffffu, acc, o);
    if ((t & 31) == 0) s_red[t >> 5] = acc;
    __syncthreads();
    if (t < 8) {
        float v = s_red[t];
#pragma unroll
        for (int o = 4; o > 0; o >>= 1)
            v += __shfl_xor_sync(0xffu, v, o);
        if (t == 0) atomicAdd(&g_vtot, v);
    }
}

// ---------------- finalize ----------------
__global__ void k_final(float* __restrict__ out) {
    if (threadIdx.x == 0)
        out[0] = (g_vtot + g_extra) * (1.f / BQ);
}

// ---------------- entry point ----------------
extern "C" void kernel_launch(void* const* d_in, const int* in_sizes, int n_in,
                              void* d_out, int out_size) {
    const float* data   = (const float*)d_in[0];
    const int*   labels = (const int*)d_in[1];
    float* out = (float*)d_out;

    k_init<<<6, 256>>>();

    dim3 cgrid(NPIX / (256 * 128), BQ);     // 16 blocks x 4 images
    k_count<<<cgrid, 256>>>(labels);

    dim3 agrid(ABLK_X, BQ);
    k_accum<<<agrid, 256>>>(data, labels);

    k_centers<<<1, 256>>>();

    dim3 vgrid(NPIX / 2048, BQ);
    k_var<<<vgrid, 256>>>(data, labels);

    k_final<<<1, 32>>>(out);
}

// round 8
// speedup vs baseline: 1.8054x; 1.0210x over previous
#include <cuda_runtime.h>
#include <cstdint>

// Problem constants (fixed shapes)
#define BQ   4
#define KC   24
#define DD   16
#define NPIX (512 * 1024)
#define KP   17

// k_accum tiling
#define TILE        256
#define QROW        17
#define TILES_IMG   (NPIX / TILE)         // 2048 tiles per image
#define ABLK_X      185                   // 185*4 = 740 blocks ≈ 5/SM one wave

#define CNT_BLKS    16                    // k_count blocks per image

// ---------------- device scratch ----------------
__device__ float g_sums[BQ * KC * DD];
__device__ int   g_cnt_part[BQ * CNT_BLKS * KC];
__device__ float g_counts[BQ * KC];
__device__ float g_centers[BQ * KC * DD];
__device__ float g_invc[BQ * KC];
__device__ float g_vtot;
__device__ float g_extra;
__device__ unsigned int g_done;

// ---------------- pass 0: label histogram (per-block partials, no init needed)
__global__ void __launch_bounds__(256) k_count(const int* __restrict__ labels) {
    __shared__ int s_h[8][KC + 8];
    const int t = threadIdx.x;
    const int w = t >> 5;
    const int b = blockIdx.y;
    const int* lptr = labels + (size_t)b * NPIX;

    // block (0,0) zeroes g_sums (consumed by k_accum's atomics, next kernel)
    if (blockIdx.x == 0 && b == 0) {
        for (int i = t; i < BQ * KC * DD; i += 256) g_sums[i] = 0.f;
    }

    for (int i = t; i < 8 * (KC + 8); i += 256)
        (&s_h[0][0])[i] = 0;
    __syncthreads();

    const int base = blockIdx.x * (256 * 32);
#pragma unroll 4
    for (int i = 0; i < 32; i++) {
        const int4 l4 = reinterpret_cast<const int4*>(lptr)[base + i * 256 + t];
        atomicAdd(&s_h[w][l4.x], 1);
        atomicAdd(&s_h[w][l4.y], 1);
        atomicAdd(&s_h[w][l4.z], 1);
        atomicAdd(&s_h[w][l4.w], 1);
    }
    __syncthreads();

    if (t < KC) {
        int s = 0;
#pragma unroll
        for (int c = 0; c < 8; c++) s += s_h[c][t];
        g_cnt_part[(b * CNT_BLKS + blockIdx.x) * KC + t] = s;   // plain store
    }
}

// ---------------- pass 1: half-warp smem RMW, conflict-free staging ----------
__global__ void __launch_bounds__(256) k_accum(const float* __restrict__ data,
                                               const int*  __restrict__ labels) {
    __shared__ float s_data[TILE * QROW];
    __shared__ float s_acc[8 * 2 * KC * DD];

    const int t = threadIdx.x;
    const int w = t >> 5;
    const int lane = t & 31;
    const int half = lane >> 4;
    const int dlane = lane & 15;

    const int b = blockIdx.y;
    const float* dptr = data + (size_t)b * DD * NPIX;
    const int*   lptr = labels + (size_t)b * NPIX;

    for (int i = t; i < 8 * 2 * KC * DD; i += 256) s_acc[i] = 0.f;
    __syncthreads();

    const int drot = (dlane + (w & 3)) & 15;
    const float* myrow0 = &s_data[(w * 32 + half) * QROW + drot];
    float* accb = &s_acc[((w * 2 + half) * KC) * DD + dlane];

    for (int tile = blockIdx.x; tile < TILES_IMG; tile += ABLK_X) {
        const int p4base = tile * (TILE / 4);
        const int labReg = lptr[tile * TILE + w * 32 + lane];

#pragma unroll
        for (int i = 0; i < 4; i++) {
            const int idx = t + i * 256;
            const int d  = idx >> 6;
            const int pv = idx & 63;
            const float4 v =
                reinterpret_cast<const float4*>(dptr + (size_t)d * NPIX)[p4base + pv];
            const int dd = (d + ((pv >> 3) & 3)) & 15;
            float* rp = &s_data[(pv * 4) * QROW + dd];
            rp[0 * QROW] = v.x;
            rp[1 * QROW] = v.y;
            rp[2 * QROW] = v.z;
            rp[3 * QROW] = v.w;
        }
        __syncthreads();

#pragma unroll
        for (int i = 0; i < 16; i++) {
            const int myl = __shfl_sync(0xffffffffu, labReg, 2 * i + half);
            const float v = myrow0[i * (2 * QROW)];
            float* pa = accb + myl * DD;
            *pa += v;
        }
        __syncthreads();
    }

    for (int o = t; o < KC * DD; o += 256) {
        float s = 0.f;
#pragma unroll
        for (int c = 0; c < 16; c++) s += s_acc[c * (KC * DD) + o];
        atomicAdd(&g_sums[b * KC * DD + o], s);
    }
}

// ---------------- centers + dist + reg; zero vtot/ticket; reciprocal divide --
__global__ void __launch_bounds__(256) k_centers() {
    __shared__ float s_c[BQ * KC * DD];
    __shared__ float s_ic[BQ * KC];
    __shared__ float s_red[8];
    const int t = threadIdx.x;

    if (t == 0) { g_vtot = 0.f; g_done = 0u; }

    // counts from partials, 96 divisions total
    if (t < BQ * KC) {
        const int b = t / KC, k = t - b * KC;
        int s = 0;
#pragma unroll
        for (int c = 0; c < CNT_BLKS; c++)
            s += g_cnt_part[(b * CNT_BLKS + c) * KC + k];
        const float cnt = (float)s;
        const float inv = 1.f / cnt;
        g_counts[t] = cnt;
        g_invc[t] = inv;
        s_ic[t] = inv;
    }
    __syncthreads();

    for (int i = t; i < BQ * KC * DD; i += 256) {
        const float c = g_sums[i] * s_ic[i >> 4];
        s_c[i] = c;
        g_centers[i] = c;
    }
    __syncthreads();

    const float inv_pairs = 1.f / (2.f * KC * (KC - 1));
    float acc = 0.f;
    for (int i = t; i < BQ * KC * KC; i += 256) {
        const int b = i / (KC * KC);
        const int r = i - b * KC * KC;
        const int k1 = r / KC, k2 = r - k1 * KC;
        const float* c1 = &s_c[(b * KC + k1) * DD];
        const float* c2 = &s_c[(b * KC + k2) * DD];
        float sq = 0.f;
#pragma unroll
        for (int d = 0; d < DD; d++) { const float df = c1[d] - c2[d]; sq += df * df; }
        const float cd = (k1 == k2) ? 0.f : sqrtf(sq);
        const float h  = fmaxf(2.f - cd, 0.f);
        acc += h * h * inv_pairs;
    }
    for (int i = t; i < BQ * KC; i += 256) {
        const float* c = &s_c[i * DD];
        float sq = 0.f;
#pragma unroll
        for (int d = 0; d < DD; d++) sq += c[d] * c[d];
        acc += sqrtf(sq) * (1.f / KC);
    }

#pragma unroll
    for (int o = 16; o > 0; o >>= 1)
        acc += __shfl_xor_sync(0xffffffffu, acc, o);
    if ((t & 31) == 0) s_red[t >> 5] = acc;
    __syncthreads();
    if (t < 8) {
        float v = s_red[t];
#pragma unroll
        for (int o = 4; o > 0; o >>= 1)
            v += __shfl_xor_sync(0xffu, v, o);
        if (t == 0) g_extra = v;
    }
}

// ---------------- pass 2: hinged variance + fused finalize ----------
__global__ void __launch_bounds__(256) k_var(const float* __restrict__ data,
                                             const int*  __restrict__ labels,
                                             float* __restrict__ out,
                                             int nblocks) {
    __shared__ float s_c[KC * KP];
    __shared__ float s_ic[KC];
    __shared__ float s_red[8];
    __shared__ bool s_last;
    const int t = threadIdx.x;
    const int b = blockIdx.y;

    for (int i = t; i < KC * DD; i += 256)
        s_c[(i >> 4) * KP + (i & 15)] = g_centers[b * KC * DD + i];
    if (t < KC) s_ic[t] = g_invc[b * KC + t];
    __syncthreads();

    const float* dptr = data + (size_t)b * DD * NPIX;
    const int*   lptr = labels + (size_t)b * NPIX;

    const int bx = gridDim.x - 1 - blockIdx.x;   // reversed: L2 reuse from pass 1
    const int vbase = bx * (256 * 2);

    float acc = 0.f;
#pragma unroll
    for (int it = 0; it < 2; it++) {
        const int vn = vbase + it * 256 + t;
        const int4 l4 = reinterpret_cast<const int4*>(lptr)[vn];
        const int o0 = l4.x * KP, o1 = l4.y * KP, o2 = l4.z * KP, o3 = l4.w * KP;
        float s0 = 0.f, s1 = 0.f, s2 = 0.f, s3 = 0.f;
#pragma unroll
        for (int d = 0; d < DD; d++) {
            const float4 v =
                reinterpret_cast<const float4*>(dptr + (size_t)d * NPIX)[vn];
            const float a0 = v.x - s_c[o0 + d]; s0 += a0 * a0;
            const float a1 = v.y - s_c[o1 + d]; s1 += a1 * a1;
            const float a2 = v.z - s_c[o2 + d]; s2 += a2 * a2;
            const float a3 = v.w - s_c[o3 + d]; s3 += a3 * a3;
        }
        const float h0 = fmaxf(sqrtf(s0) - 1.f, 0.f);
        const float h1 = fmaxf(sqrtf(s1) - 1.f, 0.f);
        const float h2 = fmaxf(sqrtf(s2) - 1.f, 0.f);
        const float h3 = fmaxf(sqrtf(s3) - 1.f, 0.f);
        acc += h0 * h0 * s_ic[l4.x];
        acc += h1 * h1 * s_ic[l4.y];
        acc += h2 * h2 * s_ic[l4.z];
        acc += h3 * h3 * s_ic[l4.w];
    }

#pragma unroll
    for (int o = 16; o > 0; o >>= 1)
        acc += __shfl_xor_sync(0xffffffffu, acc, o);
    if ((t & 31) == 0) s_red[t >> 5] = acc;
    __syncthreads();
    if (t < 8) {
        float v = s_red[t];
#pragma unroll
        for (int o = 4; o > 0; o >>= 1)
            v += __shfl_xor_sync(0xffu, v, o);
        if (t == 0) {
            atomicAdd(&g_vtot, v);
            __threadfence();
            const unsigned ticket = atomicAdd(&g_done, 1u);
            s_last = (ticket == (unsigned)(nblocks - 1));
        }
    }
    __syncthreads();
    if (s_last && t == 0) {
        const float vt = *(volatile float*)&g_vtot;
        out[0] = (vt + g_extra) * (1.f / BQ);
    }
}

// ---------------- entry point ----------------
extern "C" void kernel_launch(void* const* d_in, const int* in_sizes, int n_in,
                              void* d_out, int out_size) {
    const float* data   = (const float*)d_in[0];
    const int*   labels = (const int*)d_in[1];
    float* out = (float*)d_out;

    dim3 cgrid(CNT_BLKS, BQ);
    k_count<<<cgrid, 256>>>(labels);

    dim3 agrid(ABLK_X, BQ);
    k_accum<<<agrid, 256>>>(data, labels);

    k_centers<<<1, 256>>>();

    dim3 vgrid(NPIX / 2048, BQ);
    k_var<<<vgrid, 256>>>(data, labels, out, (NPIX / 2048) * BQ);
}